// round 13
// baseline (speedup 1.0000x reference)
#include <cuda_runtime.h>
#include <cuda_fp16.h>
#include <cstdint>

// ---------------- problem constants ----------------
#define NBATCH   128
#define NM       100
#define NE       50
#define NS       25
#define NPB      175
#define NNODES   (NBATCH*NPB)   // 22400
#define HDIM     768
#define TDIM     256
#define DDIM     1024
#define OUTF     768
#define NLAYER   3
#define NEDGE    716800
#define NENT     (NBATCH*NE)    // 6400
#define LRELU    0.01f
#define LN_EPS   1e-5f

// ---------------- device scratch ----------------
// NOTE: zero-initialized at module load; kernels re-zero what they consume so
// every graph replay sees the same initial state.
__device__ __align__(16) __half  g_xh[(size_t)NNODES * DDIM];   // activations (fp16)
__device__ __align__(16) __half  g_ah[(size_t)NNODES * DDIM];   // aggregated features (fp16)
__device__ __align__(16) __half  g_wt[(size_t)NLAYER * DDIM * DDIM];
__device__ __align__(16) __half  g_fcw[(size_t)OUTF * DDIM];
__device__ int   g_deg_out[NNODES];
__device__ int   g_deg_in[NNODES];
__device__ float g_dinv_out[NNODES];
__device__ float g_dinv_in[NNODES];
__device__ int   g_offs[NNODES + 1];
__device__ int   g_cursor[NNODES];
__device__ __align__(8) int2 g_edge[NEDGE];    // (src col, weight as int bits)

// ---------------- helpers ----------------
__device__ __forceinline__ uint32_t smem_u32(const void* p) {
    uint32_t a;
    asm("{ .reg .u64 t; cvta.to.shared.u64 t, %1; cvt.u32.u64 %0, t; }" : "=r"(a) : "l"(p));
    return a;
}
#define LDSM4(r, addr) \
    asm volatile("ldmatrix.sync.aligned.m8n8.x4.shared.b16 {%0,%1,%2,%3}, [%4];" \
        : "=r"((r)[0]), "=r"((r)[1]), "=r"((r)[2]), "=r"((r)[3]) : "r"(addr))
#define MMA16816(d, a, b) \
    asm volatile("mma.sync.aligned.m16n8k16.row.col.f32.f16.f16.f32 " \
        "{%0,%1,%2,%3}, {%4,%5,%6,%7}, {%8,%9}, {%0,%1,%2,%3};" \
        : "+f"((d)[0]), "+f"((d)[1]), "+f"((d)[2]), "+f"((d)[3]) \
        : "r"((a)[0]), "r"((a)[1]), "r"((a)[2]), "r"((a)[3]), "r"((b)[0]), "r"((b)[1]))
#define CP16(dst, src) \
    asm volatile("cp.async.cg.shared.global [%0], [%1], 16;" :: "r"(dst), "l"(src) : "memory")
#define CP_COMMIT() asm volatile("cp.async.commit_group;" ::: "memory")
#define CP_WAIT1()  asm volatile("cp.async.wait_group 1;" ::: "memory")

// ---------------- fused prep: build_ln + weight transposes ----------------
#define TBLKS (3 * 1024 + 24 * 32)   // 3840

__global__ void __launch_bounds__(256)
fused_prep_kernel(const float* __restrict__ mhs, const float* __restrict__ ehs,
                  const float* __restrict__ shs, const float* __restrict__ temb,
                  const float* __restrict__ scale, const float* __restrict__ bias,
                  const float* __restrict__ gw, const float* __restrict__ fcw) {
    __shared__ float tile[32][33];
    __shared__ float sh1[8], sh2[8], s_mu, s_r;
    int bx = blockIdx.x;
    int t = threadIdx.x;

    if (bx < NNODES) {
        // ---- build node features + layernorm (fp16 out) ----
        int node = bx;
        int b = node / NPB;
        int i = node - b * NPB;
        int c = t * 4;

        const float* src;
        int type;
        if (i < NM)           { type = 0; src = mhs + ((size_t)b * NM + i) * HDIM; }
        else if (i < NM + NE) { type = 1; src = ehs + ((size_t)b * NE + (i - NM)) * HDIM; }
        else                  { type = 2; src = shs + ((size_t)b * NS + (i - NM - NE)) * HDIM; }

        float4 v;
        if (c < HDIM) v = *(const float4*)(src + c);
        else          v = *(const float4*)(temb + type * TDIM + (c - HDIM));

        float s1 = v.x + v.y + v.z + v.w;
        float s2 = v.x * v.x + v.y * v.y + v.z * v.z + v.w * v.w;
        int lane = t & 31, wid = t >> 5;
#pragma unroll
        for (int o = 16; o > 0; o >>= 1) {
            s1 += __shfl_down_sync(0xFFFFFFFFu, s1, o);
            s2 += __shfl_down_sync(0xFFFFFFFFu, s2, o);
        }
        if (lane == 0) { sh1[wid] = s1; sh2[wid] = s2; }
        __syncthreads();
        if (wid == 0) {
            s1 = (lane < 8) ? sh1[lane] : 0.f;
            s2 = (lane < 8) ? sh2[lane] : 0.f;
#pragma unroll
            for (int o = 4; o > 0; o >>= 1) {
                s1 += __shfl_down_sync(0xFFFFFFFFu, s1, o);
                s2 += __shfl_down_sync(0xFFFFFFFFu, s2, o);
            }
            if (lane == 0) {
                float mu = s1 / (float)DDIM;
                float var = s2 / (float)DDIM - mu * mu;
                s_mu = mu; s_r = rsqrtf(var + LN_EPS);
            }
        }
        __syncthreads();
        float mu = s_mu, r = s_r;
        float4 sc = *(const float4*)(scale + c);
        float4 bi = *(const float4*)(bias + c);
        __half h[4];
        h[0] = __float2half_rn((v.x - mu) * r * sc.x + bi.x);
        h[1] = __float2half_rn((v.y - mu) * r * sc.y + bi.y);
        h[2] = __float2half_rn((v.z - mu) * r * sc.z + bi.z);
        h[3] = __float2half_rn((v.w - mu) * r * sc.w + bi.w);
        *(uint2*)(g_xh + (size_t)node * DDIM + c) = *(uint2*)h;
    } else {
        // ---- transpose + fp16 convert: in [R][C] fp32 -> out [C][R] fp16 ----
        int ti = bx - NNODES;
        const float* in; __half* oh; int R, C, bxx, byy;
        if (ti < 3072) {
            int l = ti >> 10, rr = ti & 1023;
            bxx = rr & 31; byy = rr >> 5;
            in = gw + (size_t)l * DDIM * DDIM;
            oh = g_wt + (size_t)l * DDIM * DDIM;
            R = DDIM; C = DDIM;
        } else {
            int rr = ti - 3072;
            bxx = rr % 24; byy = rr / 24;
            in = fcw; oh = g_fcw; R = DDIM; C = OUTF;
        }
        int c0 = bxx * 32, r0 = byy * 32;
        int x = t & 31, y = t >> 5;
#pragma unroll
        for (int j = 0; j < 32; j += 8)
            tile[y + j][x] = in[(size_t)(r0 + y + j) * C + c0 + x];
        __syncthreads();
#pragma unroll
        for (int j = 0; j < 32; j += 8) {
            float v = tile[x][y + j];
            oh[(size_t)(c0 + y + j) * R + r0 + x] = __float2half_rn(v);
        }
    }
}

// ---------------- degree count (separate launch; deg arrays pre-zeroed) ----------------
__global__ void degree_kernel(const int* __restrict__ esrc, const int* __restrict__ edst) {
    int e = blockIdx.x * blockDim.x + threadIdx.x;
    if (e < NEDGE) { atomicAdd(&g_deg_out[esrc[e]], 1); atomicAdd(&g_deg_in[edst[e]], 1); }
}

// ---------------- scan + dinv (single pass); consumes AND re-zeroes deg arrays ----------------
#define SCAN_PER 22
__global__ void __launch_bounds__(1024) scan_dinv_kernel() {
    __shared__ int warp_sums[32];
    int t = threadIdx.x, lane = t & 31, wid = t >> 5;
    int i0 = t * SCAN_PER;

    int deg[SCAN_PER];
    int run = 0;
#pragma unroll
    for (int j = 0; j < SCAN_PER; j++) {
        int idx = i0 + j;
        int din = (idx < NNODES) ? g_deg_in[idx] : 0;
        if (idx < NNODES) {
            int dout = g_deg_out[idx]; if (dout < 1) dout = 1;
            int dc = din; if (dc < 1) dc = 1;
            g_dinv_out[idx] = rsqrtf((float)dout);
            g_dinv_in[idx]  = rsqrtf((float)dc);
            g_deg_out[idx] = 0;          // self-clean for next graph replay
            g_deg_in[idx]  = 0;
        }
        run += din;
        deg[j] = run;
    }

    int x = run;
#pragma unroll
    for (int o = 1; o < 32; o <<= 1) {
        int y = __shfl_up_sync(0xFFFFFFFFu, x, o);
        if (lane >= o) x += y;
    }
    if (lane == 31) warp_sums[wid] = x;
    __syncthreads();
    if (wid == 0) {
        int ws = warp_sums[lane];
#pragma unroll
        for (int o = 1; o < 32; o <<= 1) {
            int y = __shfl_up_sync(0xFFFFFFFFu, ws, o);
            if (lane >= o) ws += y;
        }
        warp_sums[lane] = ws;
    }
    __syncthreads();
    int excl = (x - run) + (wid > 0 ? warp_sums[wid - 1] : 0);

    if (t == 0) g_offs[0] = 0;
#pragma unroll
    for (int j = 0; j < SCAN_PER; j++) {
        int idx = i0 + j;
        if (idx < NNODES) g_offs[idx + 1] = excl + deg[j];
    }
}

__global__ void fill_csr_kernel(const int* __restrict__ esrc, const int* __restrict__ edst) {
    int e = blockIdx.x * blockDim.x + threadIdx.x;
    if (e < NEDGE) {
        int s = esrc[e], d = edst[e];
        int pos = g_offs[d] + atomicAdd(&g_cursor[d], 1);
        float w = g_dinv_out[s] * g_dinv_in[d];
        g_edge[pos] = make_int2(s, __float_as_int(w));
    }
}

// ---------------- aggregation: gather fp16 x (uint4/thread), fp32 acc, fp16 out ----------------
// 128 threads/block, 8 halfs per thread. Layer-1 pass also re-zeroes g_cursor.
template<bool ENT_ONLY>
__global__ void __launch_bounds__(128) aggregate_kernel() {
    int orow = blockIdx.x;
    int node = ENT_ONLY ? ((orow / NE) * NPB + NM + (orow % NE)) : orow;
    int t = threadIdx.x;
    int beg = g_offs[node], end = g_offs[node + 1];

    if (!ENT_ONLY && t == 0) g_cursor[node] = 0;

    __shared__ int2 s_e[128];
    const uint4* x4 = (const uint4*)g_xh;   // row pitch = 128 uint4

    float2 a0 = make_float2(0.f, 0.f), a1 = a0, a2 = a0, a3 = a0;
    for (int base = beg; base < end; base += 128) {
        int n = end - base; if (n > 128) n = 128;
        if (t < n) s_e[t] = g_edge[base + t];
        __syncthreads();
#pragma unroll 4
        for (int i = 0; i < n; i++) {
            int2 e = s_e[i];
            float ww = __int_as_float(e.y);
            uint4 u = x4[e.x * 128 + t];
            float2 f0 = __half22float2(*(__half2*)&u.x);
            float2 f1 = __half22float2(*(__half2*)&u.y);
            float2 f2 = __half22float2(*(__half2*)&u.z);
            float2 f3 = __half22float2(*(__half2*)&u.w);
            a0.x += ww * f0.x; a0.y += ww * f0.y;
            a1.x += ww * f1.x; a1.y += ww * f1.y;
            a2.x += ww * f2.x; a2.y += ww * f2.y;
            a3.x += ww * f3.x; a3.y += ww * f3.y;
        }
        __syncthreads();
    }
    uint4 o;
    *(__half2*)&o.x = __floats2half2_rn(a0.x, a0.y);
    *(__half2*)&o.y = __floats2half2_rn(a1.x, a1.y);
    *(__half2*)&o.z = __floats2half2_rn(a2.x, a2.y);
    *(__half2*)&o.w = __floats2half2_rn(a3.x, a3.y);
    ((uint4*)g_ah)[(size_t)orow * 128 + t] = o;
}

// ---------------- HMMA fp16 GEMM: CTA 128x128, warp tile 64x32, BK=64, 3-stage ----------------
#define BM 128
#define BN 128
#define BK 64
#define SKB 72                             // 144 B row stride; conflict-free ldmatrix
#define TILE_E (BM * SKB)                  // 9216 halfs = 18432 B
#define NST 3
#define GEMM_SMEM (NST * 2 * TILE_E * 2)   // 110592 B

template<bool OUT_HALF>
__global__ void __launch_bounds__(256)
mma_gemm_kernel(const __half* __restrict__ A, const __half* __restrict__ B,
                const float* __restrict__ bias, void* __restrict__ CoutV,
                int Nout, int relu) {
    extern __shared__ __half sm[];
    uint32_t sbase = smem_u32(sm);

    const int t = threadIdx.x, lane = t & 31, wid = t >> 5;
    const int wm = wid & 1, wn = wid >> 1;
    const int row0 = blockIdx.y * BM, col0 = blockIdx.x * BN;

    // staging: 2 threads/row, 4 uint4 each (64 halfs/row per chunk)
    const int r = t >> 1, c4 = (t & 1) * 4;
    const uint4* gA = (const uint4*)A + (size_t)(row0 + r) * 128;  // row pitch: 1024 halfs
    const uint4* gB = (const uint4*)B + (size_t)(col0 + r) * 128;
    const uint32_t soA = (uint32_t)(r * SKB + c4 * 8) * 2;         // bytes; +16 per uint4

    float acc[4][4][4];
#pragma unroll
    for (int mt = 0; mt < 4; mt++)
#pragma unroll
        for (int nt = 0; nt < 4; nt++)
#pragma unroll
            for (int k = 0; k < 4; k++) acc[mt][nt][k] = 0.f;

    const int nk = 1024 / BK;   // 16

#define ISSUE(k0, st) do { \
        int off = (k0) * 8 + c4; \
        uint32_t sb_ = sbase + (uint32_t)((st) * 2 * TILE_E * 2); \
        CP16(sb_ + soA +  0, gA + off);     CP16(sb_ + soA + 16, gA + off + 1); \
        CP16(sb_ + soA + 32, gA + off + 2); CP16(sb_ + soA + 48, gA + off + 3); \
        uint32_t sbB = sb_ + TILE_E * 2; \
        CP16(sbB + soA +  0, gB + off);     CP16(sbB + soA + 16, gB + off + 1); \
        CP16(sbB + soA + 32, gB + off + 2); CP16(sbB + soA + 48, gB + off + 3); \
    } while (0)

    ISSUE(0, 0); CP_COMMIT();
    ISSUE(1, 1); CP_COMMIT();

    const int asel = lane >> 3;
    const int arowoff = (asel & 1) * 8 + (lane & 7);
    const int akadd = (asel >> 1) * 8;
    const int brow2 = ((lane >> 4) & 1) * 8 + (lane & 7);
    const int bk2   = ((lane >> 3) & 1) * 8;

    for (int k0 = 0; k0 < nk; k0++) {
        CP_WAIT1();
        __syncthreads();
        if (k0 + 2 < nk) ISSUE(k0 + 2, (k0 + 2) % 3);
        CP_COMMIT();

        uint32_t base = sbase + (uint32_t)((k0 % 3) * 2 * TILE_E * 2);
        uint32_t bA = base;
        uint32_t bB = base + TILE_E * 2;
#pragma unroll
        for (int ks = 0; ks < 4; ks++) {
            const int kk = ks * 16;
            uint32_t ah[4][4], bb[4][2];
#pragma unroll
            for (int mt = 0; mt < 4; mt++) {
                int rrow = wm * 64 + mt * 16 + arowoff;
                LDSM4(ah[mt], bA + (uint32_t)((rrow * SKB + kk + akadd) * 2));
            }
#pragma unroll
            for (int ntp = 0; ntp < 2; ntp++) {
                int nrow = wn * 32 + ntp * 16 + brow2;
                LDSM4(&bb[2 * ntp][0], bB + (uint32_t)((nrow * SKB + kk + bk2) * 2));
            }
#pragma unroll
            for (int mt = 0; mt < 4; mt++)
#pragma unroll
                for (int nt = 0; nt < 4; nt++) MMA16816(acc[mt][nt], ah[mt], bb[nt]);
        }
    }
#undef ISSUE

    // epilogue
    const int rbase = row0 + wm * 64 + (lane >> 2);
    const int cbase = col0 + wn * 32 + (lane & 3) * 2;
#pragma unroll
    for (int nt = 0; nt < 4; nt++) {
        int col = cbase + nt * 8;
        float b0 = bias[col], b1 = bias[col + 1];
#pragma unroll
        for (int mt = 0; mt < 4; mt++) {
            int rrow = rbase + mt * 16;
            float v0 = acc[mt][nt][0] + b0;
            float v1 = acc[mt][nt][1] + b1;
            float v2 = acc[mt][nt][2] + b0;
            float v3 = acc[mt][nt][3] + b1;
            if (relu) {
                v0 = (v0 > 0.f) ? v0 : LRELU * v0;
                v1 = (v1 > 0.f) ? v1 : LRELU * v1;
                v2 = (v2 > 0.f) ? v2 : LRELU * v2;
                v3 = (v3 > 0.f) ? v3 : LRELU * v3;
            }
            if (OUT_HALF) {
                __half* C = (__half*)CoutV;
                *(__half2*)(C + (size_t)rrow * Nout + col) = __floats2half2_rn(v0, v1);
                *(__half2*)(C + (size_t)(rrow + 8) * Nout + col) = __floats2half2_rn(v2, v3);
            } else {
                float* C = (float*)CoutV;
                *(float2*)(C + (size_t)rrow * Nout + col) = make_float2(v0, v1);
                *(float2*)(C + (size_t)(rrow + 8) * Nout + col) = make_float2(v2, v3);
            }
        }
    }
}

// ---------------- launch ----------------
extern "C" void kernel_launch(void* const* d_in, const int* in_sizes, int n_in,
                              void* d_out, int out_size) {
    const float* mhs  = (const float*)d_in[0];
    const float* ehs  = (const float*)d_in[1];
    const float* shs  = (const float*)d_in[2];
    const int*   esrc = (const int*)d_in[3];
    const int*   edst = (const int*)d_in[4];
    const float* temb = (const float*)d_in[5];
    const float* lns  = (const float*)d_in[6];
    const float* lnb  = (const float*)d_in[7];
    const float* gw   = (const float*)d_in[8];
    const float* gb   = (const float*)d_in[9];
    const float* fcw  = (const float*)d_in[10];
    const float* fcb  = (const float*)d_in[11];
    float* out = (float*)d_out;

    cudaFuncSetAttribute(mma_gemm_kernel<true>,
                         cudaFuncAttributeMaxDynamicSharedMemorySize, GEMM_SMEM);
    cudaFuncSetAttribute(mma_gemm_kernel<false>,
                         cudaFuncAttributeMaxDynamicSharedMemorySize, GEMM_SMEM);

    __half *wt, *fcw_h, *ah, *xh;
    cudaGetSymbolAddress((void**)&wt,    g_wt);
    cudaGetSymbolAddress((void**)&fcw_h, g_fcw);
    cudaGetSymbolAddress((void**)&ah,    g_ah);
    cudaGetSymbolAddress((void**)&xh,    g_xh);

    // launches 0-3: prep / degree / scan / CSR fill
    fused_prep_kernel<<<NNODES + TBLKS, 256>>>(mhs, ehs, shs, temb, lns, lnb, gw, fcw);
    degree_kernel<<<(NEDGE + 255) / 256, 256>>>(esrc, edst);
    scan_dinv_kernel<<<1, 1024>>>();
    fill_csr_kernel<<<(NEDGE + 255) / 256, 256>>>(esrc, edst);

    // layers 1-2: full node set (launch 4 = aggregate<0>, launch 5 = GEMM -> ncu slot)
    for (int l = 0; l < NLAYER - 1; l++) {
        aggregate_kernel<false><<<NNODES, 128>>>();
        mma_gemm_kernel<true><<<dim3(DDIM / BN, NNODES / BM), 256, GEMM_SMEM>>>(
            ah, wt + (size_t)l * DDIM * DDIM, gb + (size_t)l * DDIM, xh, DDIM, /*relu=*/1);
    }

    // layer 3: entity dst rows only (compact M = 6400)
    aggregate_kernel<true><<<NENT, 128>>>();
    mma_gemm_kernel<true><<<dim3(DDIM / BN, NENT / BM), 256, GEMM_SMEM>>>(
        ah, wt + (size_t)2 * DDIM * DDIM, gb + (size_t)2 * DDIM, xh, DDIM, /*relu=*/1);

    // fc on compact entity rows
    mma_gemm_kernel<false><<<dim3(OUTF / BN, NENT / BM), 256, GEMM_SMEM>>>(
        xh, fcw_h, fcb, out, OUTF, /*relu=*/0);
}

// round 14
// speedup vs baseline: 1.0916x; 1.0916x over previous
#include <cuda_runtime.h>
#include <cuda_fp16.h>
#include <cstdint>

// ---------------- problem constants ----------------
#define NBATCH   128
#define NM       100
#define NE       50
#define NS       25
#define NPB      175
#define NNODES   (NBATCH*NPB)   // 22400
#define HDIM     768
#define TDIM     256
#define DDIM     1024
#define OUTF     768
#define NLAYER   3
#define NEDGE    716800
#define NENT     (NBATCH*NE)    // 6400
#define LRELU    0.01f
#define LN_EPS   1e-5f

// ---------------- device scratch ----------------
// NOTE: zero-initialized at module load; kernels re-zero what they consume so
// every graph replay sees the same initial state.
__device__ __align__(16) __half  g_xh[(size_t)NNODES * DDIM];   // activations (fp16)
__device__ __align__(16) __half  g_ah[(size_t)NNODES * DDIM];   // aggregated features (fp16)
__device__ __align__(16) __half  g_wt[(size_t)NLAYER * DDIM * DDIM];
__device__ __align__(16) __half  g_fcw[(size_t)OUTF * DDIM];
__device__ int   g_deg_out[NNODES];
__device__ int   g_deg_in[NNODES];
__device__ float g_dinv_out[NNODES];
__device__ float g_dinv_in[NNODES];
__device__ int   g_offs[NNODES + 1];
__device__ int   g_cursor[NNODES];
__device__ __align__(8) int2 g_edge[NEDGE];    // (src col, weight as int bits)

// ---------------- helpers ----------------
__device__ __forceinline__ uint32_t smem_u32(const void* p) {
    uint32_t a;
    asm("{ .reg .u64 t; cvta.to.shared.u64 t, %1; cvt.u32.u64 %0, t; }" : "=r"(a) : "l"(p));
    return a;
}
#define LDSM4(r, addr) \
    asm volatile("ldmatrix.sync.aligned.m8n8.x4.shared.b16 {%0,%1,%2,%3}, [%4];" \
        : "=r"((r)[0]), "=r"((r)[1]), "=r"((r)[2]), "=r"((r)[3]) : "r"(addr))
#define MMA16816(d, a, b) \
    asm volatile("mma.sync.aligned.m16n8k16.row.col.f32.f16.f16.f32 " \
        "{%0,%1,%2,%3}, {%4,%5,%6,%7}, {%8,%9}, {%0,%1,%2,%3};" \
        : "+f"((d)[0]), "+f"((d)[1]), "+f"((d)[2]), "+f"((d)[3]) \
        : "r"((a)[0]), "r"((a)[1]), "r"((a)[2]), "r"((a)[3]), "r"((b)[0]), "r"((b)[1]))
#define CP16(dst, src) \
    asm volatile("cp.async.cg.shared.global [%0], [%1], 16;" :: "r"(dst), "l"(src) : "memory")
#define CP_COMMIT() asm volatile("cp.async.commit_group;" ::: "memory")
#define CP_WAIT2()  asm volatile("cp.async.wait_group 2;" ::: "memory")

// ---------------- fused prep: build_ln + weight transposes + degree count ----------------
#define TBLKS (3 * 1024 + 24 * 32)   // 3840
#define DBLKS ((NEDGE + 255) / 256)  // 2800

__global__ void __launch_bounds__(256)
fused_prep_kernel(const float* __restrict__ mhs, const float* __restrict__ ehs,
                  const float* __restrict__ shs, const float* __restrict__ temb,
                  const float* __restrict__ scale, const float* __restrict__ bias,
                  const float* __restrict__ gw, const float* __restrict__ fcw,
                  const int* __restrict__ esrc, const int* __restrict__ edst) {
    __shared__ float tile[32][33];
    __shared__ float sh1[8], sh2[8], s_mu, s_r;
    int bx = blockIdx.x;
    int t = threadIdx.x;

    if (bx < NNODES) {
        // ---- build node features + layernorm (fp16 out) ----
        int node = bx;
        int b = node / NPB;
        int i = node - b * NPB;
        int c = t * 4;

        const float* src;
        int type;
        if (i < NM)           { type = 0; src = mhs + ((size_t)b * NM + i) * HDIM; }
        else if (i < NM + NE) { type = 1; src = ehs + ((size_t)b * NE + (i - NM)) * HDIM; }
        else                  { type = 2; src = shs + ((size_t)b * NS + (i - NM - NE)) * HDIM; }

        float4 v;
        if (c < HDIM) v = *(const float4*)(src + c);
        else          v = *(const float4*)(temb + type * TDIM + (c - HDIM));

        float s1 = v.x + v.y + v.z + v.w;
        float s2 = v.x * v.x + v.y * v.y + v.z * v.z + v.w * v.w;
        int lane = t & 31, wid = t >> 5;
#pragma unroll
        for (int o = 16; o > 0; o >>= 1) {
            s1 += __shfl_down_sync(0xFFFFFFFFu, s1, o);
            s2 += __shfl_down_sync(0xFFFFFFFFu, s2, o);
        }
        if (lane == 0) { sh1[wid] = s1; sh2[wid] = s2; }
        __syncthreads();
        if (wid == 0) {
            s1 = (lane < 8) ? sh1[lane] : 0.f;
            s2 = (lane < 8) ? sh2[lane] : 0.f;
#pragma unroll
            for (int o = 4; o > 0; o >>= 1) {
                s1 += __shfl_down_sync(0xFFFFFFFFu, s1, o);
                s2 += __shfl_down_sync(0xFFFFFFFFu, s2, o);
            }
            if (lane == 0) {
                float mu = s1 / (float)DDIM;
                float var = s2 / (float)DDIM - mu * mu;
                s_mu = mu; s_r = rsqrtf(var + LN_EPS);
            }
        }
        __syncthreads();
        float mu = s_mu, r = s_r;
        float4 sc = *(const float4*)(scale + c);
        float4 bi = *(const float4*)(bias + c);
        __half h[4];
        h[0] = __float2half_rn((v.x - mu) * r * sc.x + bi.x);
        h[1] = __float2half_rn((v.y - mu) * r * sc.y + bi.y);
        h[2] = __float2half_rn((v.z - mu) * r * sc.z + bi.z);
        h[3] = __float2half_rn((v.w - mu) * r * sc.w + bi.w);
        *(uint2*)(g_xh + (size_t)node * DDIM + c) = *(uint2*)h;
    } else if (bx < NNODES + TBLKS) {
        // ---- transpose + fp16 convert: in [R][C] fp32 -> out [C][R] fp16 ----
        int ti = bx - NNODES;
        const float* in; __half* oh; int R, C, bxx, byy;
        if (ti < 3072) {
            int l = ti >> 10, rr = ti & 1023;
            bxx = rr & 31; byy = rr >> 5;
            in = gw + (size_t)l * DDIM * DDIM;
            oh = g_wt + (size_t)l * DDIM * DDIM;
            R = DDIM; C = DDIM;
        } else {
            int rr = ti - 3072;
            bxx = rr % 24; byy = rr / 24;
            in = fcw; oh = g_fcw; R = DDIM; C = OUTF;
        }
        int c0 = bxx * 32, r0 = byy * 32;
        int x = t & 31, y = t >> 5;
#pragma unroll
        for (int j = 0; j < 32; j += 8)
            tile[y + j][x] = in[(size_t)(r0 + y + j) * C + c0 + x];
        __syncthreads();
#pragma unroll
        for (int j = 0; j < 32; j += 8) {
            float v = tile[x][y + j];
            oh[(size_t)(c0 + y + j) * R + r0 + x] = __float2half_rn(v);
        }
    } else {
        // ---- degree count (deg arrays zeroed by previous replay's scan_dinv) ----
        int e = (bx - NNODES - TBLKS) * 256 + t;
        if (e < NEDGE) {
            atomicAdd(&g_deg_out[esrc[e]], 1);
            atomicAdd(&g_deg_in[edst[e]], 1);
        }
    }
}

// ---------------- scan + dinv (single pass); consumes AND re-zeroes deg arrays ----------------
#define SCAN_PER 22
__global__ void __launch_bounds__(1024) scan_dinv_kernel() {
    __shared__ int warp_sums[32];
    int t = threadIdx.x, lane = t & 31, wid = t >> 5;
    int i0 = t * SCAN_PER;

    int deg[SCAN_PER];
    int run = 0;
#pragma unroll
    for (int j = 0; j < SCAN_PER; j++) {
        int idx = i0 + j;
        int din = (idx < NNODES) ? g_deg_in[idx] : 0;
        if (idx < NNODES) {
            int dout = g_deg_out[idx]; if (dout < 1) dout = 1;
            int dc = din; if (dc < 1) dc = 1;
            g_dinv_out[idx] = rsqrtf((float)dout);
            g_dinv_in[idx]  = rsqrtf((float)dc);
            g_deg_out[idx] = 0;          // self-clean for next graph replay
            g_deg_in[idx]  = 0;
        }
        run += din;
        deg[j] = run;
    }

    int x = run;
#pragma unroll
    for (int o = 1; o < 32; o <<= 1) {
        int y = __shfl_up_sync(0xFFFFFFFFu, x, o);
        if (lane >= o) x += y;
    }
    if (lane == 31) warp_sums[wid] = x;
    __syncthreads();
    if (wid == 0) {
        int ws = warp_sums[lane];
#pragma unroll
        for (int o = 1; o < 32; o <<= 1) {
            int y = __shfl_up_sync(0xFFFFFFFFu, ws, o);
            if (lane >= o) ws += y;
        }
        warp_sums[lane] = ws;
    }
    __syncthreads();
    int excl = (x - run) + (wid > 0 ? warp_sums[wid - 1] : 0);

    if (t == 0) g_offs[0] = 0;
#pragma unroll
    for (int j = 0; j < SCAN_PER; j++) {
        int idx = i0 + j;
        if (idx < NNODES) g_offs[idx + 1] = excl + deg[j];
    }
}

__global__ void fill_csr_kernel(const int* __restrict__ esrc, const int* __restrict__ edst) {
    int e = blockIdx.x * blockDim.x + threadIdx.x;
    if (e < NEDGE) {
        int s = esrc[e], d = edst[e];
        int pos = g_offs[d] + atomicAdd(&g_cursor[d], 1);
        float w = g_dinv_out[s] * g_dinv_in[d];
        g_edge[pos] = make_int2(s, __float_as_int(w));
    }
}

// ---------------- aggregation: gather fp16 x (uint4/thread), fp32 acc, fp16 out ----------------
// 128 threads/block, 8 halfs per thread. Layer-1 pass also re-zeroes g_cursor.
template<bool ENT_ONLY>
__global__ void __launch_bounds__(128) aggregate_kernel() {
    int orow = blockIdx.x;
    int node = ENT_ONLY ? ((orow / NE) * NPB + NM + (orow % NE)) : orow;
    int t = threadIdx.x;
    int beg = g_offs[node], end = g_offs[node + 1];

    if (!ENT_ONLY && t == 0) g_cursor[node] = 0;

    __shared__ int2 s_e[128];
    const uint4* x4 = (const uint4*)g_xh;   // row pitch = 128 uint4

    float2 a0 = make_float2(0.f, 0.f), a1 = a0, a2 = a0, a3 = a0;
    for (int base = beg; base < end; base += 128) {
        int n = end - base; if (n > 128) n = 128;
        if (t < n) s_e[t] = g_edge[base + t];
        __syncthreads();
#pragma unroll 4
        for (int i = 0; i < n; i++) {
            int2 e = s_e[i];
            float ww = __int_as_float(e.y);
            uint4 u = x4[e.x * 128 + t];
            float2 f0 = __half22float2(*(__half2*)&u.x);
            float2 f1 = __half22float2(*(__half2*)&u.y);
            float2 f2 = __half22float2(*(__half2*)&u.z);
            float2 f3 = __half22float2(*(__half2*)&u.w);
            a0.x += ww * f0.x; a0.y += ww * f0.y;
            a1.x += ww * f1.x; a1.y += ww * f1.y;
            a2.x += ww * f2.x; a2.y += ww * f2.y;
            a3.x += ww * f3.x; a3.y += ww * f3.y;
        }
        __syncthreads();
    }
    uint4 o;
    *(__half2*)&o.x = __floats2half2_rn(a0.x, a0.y);
    *(__half2*)&o.y = __floats2half2_rn(a1.x, a1.y);
    *(__half2*)&o.z = __floats2half2_rn(a2.x, a2.y);
    *(__half2*)&o.w = __floats2half2_rn(a3.x, a3.y);
    ((uint4*)g_ah)[(size_t)orow * 128 + t] = o;
}

// ---------------- HMMA fp16 GEMM: CTA 128x128, warp tile 64x32, BK=32, 4-stage ----------------
#define BM 128
#define BN 128
#define BK 32
#define SKB 40
#define TILE_E (BM * SKB)                 // 5120 halfs = 10240 B
#define NST 4
#define GEMM_SMEM (NST * 2 * TILE_E * 2)  // 81920 B -> still 2 CTAs/SM

template<bool OUT_HALF>
__global__ void __launch_bounds__(256)
mma_gemm_kernel(const __half* __restrict__ A, const __half* __restrict__ B,
                const float* __restrict__ bias, void* __restrict__ CoutV,
                int Nout, int relu) {
    extern __shared__ __half sm[];
    uint32_t sbase = smem_u32(sm);

    const int t = threadIdx.x, lane = t & 31, wid = t >> 5;
    const int wm = wid & 1, wn = wid >> 1;
    const int row0 = blockIdx.y * BM, col0 = blockIdx.x * BN;

    const int r = t >> 1, cpair = (t & 1) * 2;
    const uint4* gA = (const uint4*)A + (size_t)(row0 + r) * 128;  // row pitch: 1024 halfs
    const uint4* gB = (const uint4*)B + (size_t)(col0 + r) * 128;
    const uint32_t so0 = (uint32_t)(r * SKB + cpair * 8) * 2;
    const uint32_t so1 = so0 + 16;

    float acc[4][4][4];
#pragma unroll
    for (int mt = 0; mt < 4; mt++)
#pragma unroll
        for (int nt = 0; nt < 4; nt++)
#pragma unroll
            for (int k = 0; k < 4; k++) acc[mt][nt][k] = 0.f;

    const int nk = 1024 / BK;   // 32

#define ISSUE(k0, st) do { \
        int off = (k0) * 4 + cpair; \
        uint32_t sb_ = sbase + (uint32_t)((st) * 2 * TILE_E * 2); \
        CP16(sb_ + so0, gA + off); CP16(sb_ + so1, gA + off + 1); \
        CP16(sb_ + TILE_E * 2 + so0, gB + off); CP16(sb_ + TILE_E * 2 + so1, gB + off + 1); \
    } while (0)

    ISSUE(0, 0); CP_COMMIT();
    ISSUE(1, 1); CP_COMMIT();
    ISSUE(2, 2); CP_COMMIT();

    const int asel = lane >> 3;
    const int arowoff = (asel & 1) * 8 + (lane & 7);
    const int akadd = (asel >> 1) * 8;
    const int brow2 = ((lane >> 4) & 1) * 8 + (lane & 7);
    const int bk2   = ((lane >> 3) & 1) * 8;

    for (int k0 = 0; k0 < nk; k0++) {
        CP_WAIT2();
        __syncthreads();
        if (k0 + 3 < nk) ISSUE(k0 + 3, (k0 + 3) & 3);
        CP_COMMIT();

        uint32_t base = sbase + (uint32_t)((k0 & 3) * 2 * TILE_E * 2);
        uint32_t bA = base;
        uint32_t bB = base + TILE_E * 2;
#pragma unroll
        for (int ks = 0; ks < 2; ks++) {
            const int kk = ks * 16;
            uint32_t ah[4][4], bb[4][2];
#pragma unroll
            for (int mt = 0; mt < 4; mt++) {
                int rrow = wm * 64 + mt * 16 + arowoff;
                LDSM4(ah[mt], bA + (uint32_t)((rrow * SKB + kk + akadd) * 2));
            }
#pragma unroll
            for (int ntp = 0; ntp < 2; ntp++) {
                int nrow = wn * 32 + ntp * 16 + brow2;
                LDSM4(&bb[2 * ntp][0], bB + (uint32_t)((nrow * SKB + kk + bk2) * 2));
            }
#pragma unroll
            for (int mt = 0; mt < 4; mt++)
#pragma unroll
                for (int nt = 0; nt < 4; nt++) MMA16816(acc[mt][nt], ah[mt], bb[nt]);
        }
    }
#undef ISSUE

    // epilogue
    const int rbase = row0 + wm * 64 + (lane >> 2);
    const int cbase = col0 + wn * 32 + (lane & 3) * 2;
#pragma unroll
    for (int nt = 0; nt < 4; nt++) {
        int col = cbase + nt * 8;
        float b0 = bias[col], b1 = bias[col + 1];
#pragma unroll
        for (int mt = 0; mt < 4; mt++) {
            int rrow = rbase + mt * 16;
            float v0 = acc[mt][nt][0] + b0;
            float v1 = acc[mt][nt][1] + b1;
            float v2 = acc[mt][nt][2] + b0;
            float v3 = acc[mt][nt][3] + b1;
            if (relu) {
                v0 = (v0 > 0.f) ? v0 : LRELU * v0;
                v1 = (v1 > 0.f) ? v1 : LRELU * v1;
                v2 = (v2 > 0.f) ? v2 : LRELU * v2;
                v3 = (v3 > 0.f) ? v3 : LRELU * v3;
            }
            if (OUT_HALF) {
                __half* C = (__half*)CoutV;
                *(__half2*)(C + (size_t)rrow * Nout + col) = __floats2half2_rn(v0, v1);
                *(__half2*)(C + (size_t)(rrow + 8) * Nout + col) = __floats2half2_rn(v2, v3);
            } else {
                float* C = (float*)CoutV;
                *(float2*)(C + (size_t)rrow * Nout + col) = make_float2(v0, v1);
                *(float2*)(C + (size_t)(rrow + 8) * Nout + col) = make_float2(v2, v3);
            }
        }
    }
}

// ---------------- launch ----------------
extern "C" void kernel_launch(void* const* d_in, const int* in_sizes, int n_in,
                              void* d_out, int out_size) {
    const float* mhs  = (const float*)d_in[0];
    const float* ehs  = (const float*)d_in[1];
    const float* shs  = (const float*)d_in[2];
    const int*   esrc = (const int*)d_in[3];
    const int*   edst = (const int*)d_in[4];
    const float* temb = (const float*)d_in[5];
    const float* lns  = (const float*)d_in[6];
    const float* lnb  = (const float*)d_in[7];
    const float* gw   = (const float*)d_in[8];
    const float* gb   = (const float*)d_in[9];
    const float* fcw  = (const float*)d_in[10];
    const float* fcb  = (const float*)d_in[11];
    float* out = (float*)d_out;

    cudaFuncSetAttribute(mma_gemm_kernel<true>,
                         cudaFuncAttributeMaxDynamicSharedMemorySize, GEMM_SMEM);
    cudaFuncSetAttribute(mma_gemm_kernel<false>,
                         cudaFuncAttributeMaxDynamicSharedMemorySize, GEMM_SMEM);

    __half *wt, *fcw_h, *ah, *xh;
    cudaGetSymbolAddress((void**)&wt,    g_wt);
    cudaGetSymbolAddress((void**)&fcw_h, g_fcw);
    cudaGetSymbolAddress((void**)&ah,    g_ah);
    cudaGetSymbolAddress((void**)&xh,    g_xh);

    fused_prep_kernel<<<NNODES + TBLKS + DBLKS, 256>>>(
        mhs, ehs, shs, temb, lns, lnb, gw, fcw, esrc, edst);
    scan_dinv_kernel<<<1, 1024>>>();
    fill_csr_kernel<<<(NEDGE + 255) / 256, 256>>>(esrc, edst);

    // layers 1-2: full node set
    for (int l = 0; l < NLAYER - 1; l++) {
        aggregate_kernel<false><<<NNODES, 128>>>();
        mma_gemm_kernel<true><<<dim3(DDIM / BN, NNODES / BM), 256, GEMM_SMEM>>>(
            ah, wt + (size_t)l * DDIM * DDIM, gb + (size_t)l * DDIM, xh, DDIM, /*relu=*/1);
    }

    // layer 3: entity dst rows only (compact M = 6400)
    aggregate_kernel<true><<<NENT, 128>>>();
    mma_gemm_kernel<true><<<dim3(DDIM / BN, NENT / BM), 256, GEMM_SMEM>>>(
        ah, wt + (size_t)2 * DDIM * DDIM, gb + (size_t)2 * DDIM, xh, DDIM, /*relu=*/1);

    // fc on compact entity rows
    mma_gemm_kernel<false><<<dim3(OUTF / BN, NENT / BM), 256, GEMM_SMEM>>>(
        xh, fcw_h, fcb, out, OUTF, /*relu=*/0);
}

// round 15
// speedup vs baseline: 1.1876x; 1.0880x over previous
#include <cuda_runtime.h>
#include <cuda_fp16.h>
#include <cstdint>

// ---------------- problem constants ----------------
#define NBATCH   128
#define NM       100
#define NE       50
#define NS       25
#define NPB      175
#define NNODES   (NBATCH*NPB)   // 22400
#define HDIM     768
#define TDIM     256
#define DDIM     1024
#define OUTF     768
#define NLAYER   3
#define NEDGE    716800
#define NENT     (NBATCH*NE)    // 6400
#define LRELU    0.01f
#define LN_EPS   1e-5f

// ---------------- device scratch ----------------
// NOTE: zero-initialized at module load; kernels re-zero what they consume so
// every graph replay sees the same initial state.
__device__ __align__(16) __half  g_xh[(size_t)NNODES * DDIM];   // activations (fp16)
__device__ __align__(16) __half  g_ah[(size_t)NNODES * DDIM];   // aggregated features (fp16)
__device__ __align__(16) __half  g_wt[(size_t)NLAYER * DDIM * DDIM];
__device__ __align__(16) __half  g_fcw[(size_t)OUTF * DDIM];
__device__ int   g_deg_out[NNODES];
__device__ int   g_deg_in[NNODES];
__device__ float g_dinv_out[NNODES];
__device__ float g_dinv_in[NNODES];
__device__ int   g_offs[NNODES + 1];
__device__ int   g_cursor[NNODES];
__device__ __align__(8) int2 g_edge[NEDGE];    // (src row BYTE offset = s<<11, weight bits)

// ---------------- helpers ----------------
__device__ __forceinline__ uint32_t smem_u32(const void* p) {
    uint32_t a;
    asm("{ .reg .u64 t; cvta.to.shared.u64 t, %1; cvt.u32.u64 %0, t; }" : "=r"(a) : "l"(p));
    return a;
}
#define LDSM4(r, addr) \
    asm volatile("ldmatrix.sync.aligned.m8n8.x4.shared.b16 {%0,%1,%2,%3}, [%4];" \
        : "=r"((r)[0]), "=r"((r)[1]), "=r"((r)[2]), "=r"((r)[3]) : "r"(addr))
#define MMA16816(d, a, b) \
    asm volatile("mma.sync.aligned.m16n8k16.row.col.f32.f16.f16.f32 " \
        "{%0,%1,%2,%3}, {%4,%5,%6,%7}, {%8,%9}, {%0,%1,%2,%3};" \
        : "+f"((d)[0]), "+f"((d)[1]), "+f"((d)[2]), "+f"((d)[3]) \
        : "r"((a)[0]), "r"((a)[1]), "r"((a)[2]), "r"((a)[3]), "r"((b)[0]), "r"((b)[1]))
#define CP16(dst, src) \
    asm volatile("cp.async.cg.shared.global [%0], [%1], 16;" :: "r"(dst), "l"(src) : "memory")
#define CP_COMMIT() asm volatile("cp.async.commit_group;" ::: "memory")
#define CP_WAIT2()  asm volatile("cp.async.wait_group 2;" ::: "memory")

// ---------------- fused prep: build_ln + weight transposes + degree count ----------------
#define TBLKS (3 * 1024 + 24 * 32)   // 3840
#define DBLKS ((NEDGE + 255) / 256)  // 2800

__global__ void __launch_bounds__(256)
fused_prep_kernel(const float* __restrict__ mhs, const float* __restrict__ ehs,
                  const float* __restrict__ shs, const float* __restrict__ temb,
                  const float* __restrict__ scale, const float* __restrict__ bias,
                  const float* __restrict__ gw, const float* __restrict__ fcw,
                  const int* __restrict__ esrc, const int* __restrict__ edst) {
    __shared__ float tile[32][33];
    __shared__ float sh1[8], sh2[8], s_mu, s_r;
    int bx = blockIdx.x;
    int t = threadIdx.x;

    if (bx < NNODES) {
        // ---- build node features + layernorm (fp16 out) ----
        int node = bx;
        int b = node / NPB;
        int i = node - b * NPB;
        int c = t * 4;

        const float* src;
        int type;
        if (i < NM)           { type = 0; src = mhs + ((size_t)b * NM + i) * HDIM; }
        else if (i < NM + NE) { type = 1; src = ehs + ((size_t)b * NE + (i - NM)) * HDIM; }
        else                  { type = 2; src = shs + ((size_t)b * NS + (i - NM - NE)) * HDIM; }

        float4 v;
        if (c < HDIM) v = *(const float4*)(src + c);
        else          v = *(const float4*)(temb + type * TDIM + (c - HDIM));

        float s1 = v.x + v.y + v.z + v.w;
        float s2 = v.x * v.x + v.y * v.y + v.z * v.z + v.w * v.w;
        int lane = t & 31, wid = t >> 5;
#pragma unroll
        for (int o = 16; o > 0; o >>= 1) {
            s1 += __shfl_down_sync(0xFFFFFFFFu, s1, o);
            s2 += __shfl_down_sync(0xFFFFFFFFu, s2, o);
        }
        if (lane == 0) { sh1[wid] = s1; sh2[wid] = s2; }
        __syncthreads();
        if (wid == 0) {
            s1 = (lane < 8) ? sh1[lane] : 0.f;
            s2 = (lane < 8) ? sh2[lane] : 0.f;
#pragma unroll
            for (int o = 4; o > 0; o >>= 1) {
                s1 += __shfl_down_sync(0xFFFFFFFFu, s1, o);
                s2 += __shfl_down_sync(0xFFFFFFFFu, s2, o);
            }
            if (lane == 0) {
                float mu = s1 / (float)DDIM;
                float var = s2 / (float)DDIM - mu * mu;
                s_mu = mu; s_r = rsqrtf(var + LN_EPS);
            }
        }
        __syncthreads();
        float mu = s_mu, r = s_r;
        float4 sc = *(const float4*)(scale + c);
        float4 bi = *(const float4*)(bias + c);
        __half h[4];
        h[0] = __float2half_rn((v.x - mu) * r * sc.x + bi.x);
        h[1] = __float2half_rn((v.y - mu) * r * sc.y + bi.y);
        h[2] = __float2half_rn((v.z - mu) * r * sc.z + bi.z);
        h[3] = __float2half_rn((v.w - mu) * r * sc.w + bi.w);
        *(uint2*)(g_xh + (size_t)node * DDIM + c) = *(uint2*)h;
    } else if (bx < NNODES + TBLKS) {
        // ---- transpose + fp16 convert: in [R][C] fp32 -> out [C][R] fp16 ----
        int ti = bx - NNODES;
        const float* in; __half* oh; int R, C, bxx, byy;
        if (ti < 3072) {
            int l = ti >> 10, rr = ti & 1023;
            bxx = rr & 31; byy = rr >> 5;
            in = gw + (size_t)l * DDIM * DDIM;
            oh = g_wt + (size_t)l * DDIM * DDIM;
            R = DDIM; C = DDIM;
        } else {
            int rr = ti - 3072;
            bxx = rr % 24; byy = rr / 24;
            in = fcw; oh = g_fcw; R = DDIM; C = OUTF;
        }
        int c0 = bxx * 32, r0 = byy * 32;
        int x = t & 31, y = t >> 5;
#pragma unroll
        for (int j = 0; j < 32; j += 8)
            tile[y + j][x] = in[(size_t)(r0 + y + j) * C + c0 + x];
        __syncthreads();
#pragma unroll
        for (int j = 0; j < 32; j += 8) {
            float v = tile[x][y + j];
            oh[(size_t)(c0 + y + j) * R + r0 + x] = __float2half_rn(v);
        }
    } else {
        // ---- degree count (deg arrays zeroed by previous replay's scan_dinv) ----
        int e = (bx - NNODES - TBLKS) * 256 + t;
        if (e < NEDGE) {
            atomicAdd(&g_deg_out[esrc[e]], 1);
            atomicAdd(&g_deg_in[edst[e]], 1);
        }
    }
}

// ---------------- scan + dinv (single pass); consumes AND re-zeroes deg arrays ----------------
#define SCAN_PER 22
__global__ void __launch_bounds__(1024) scan_dinv_kernel() {
    __shared__ int warp_sums[32];
    int t = threadIdx.x, lane = t & 31, wid = t >> 5;
    int i0 = t * SCAN_PER;

    int deg[SCAN_PER];
    int run = 0;
#pragma unroll
    for (int j = 0; j < SCAN_PER; j++) {
        int idx = i0 + j;
        int din = (idx < NNODES) ? g_deg_in[idx] : 0;
        if (idx < NNODES) {
            int dout = g_deg_out[idx]; if (dout < 1) dout = 1;
            int dc = din; if (dc < 1) dc = 1;
            g_dinv_out[idx] = rsqrtf((float)dout);
            g_dinv_in[idx]  = rsqrtf((float)dc);
            g_deg_out[idx] = 0;          // self-clean for next graph replay
            g_deg_in[idx]  = 0;
        }
        run += din;
        deg[j] = run;
    }

    int x = run;
#pragma unroll
    for (int o = 1; o < 32; o <<= 1) {
        int y = __shfl_up_sync(0xFFFFFFFFu, x, o);
        if (lane >= o) x += y;
    }
    if (lane == 31) warp_sums[wid] = x;
    __syncthreads();
    if (wid == 0) {
        int ws = warp_sums[lane];
#pragma unroll
        for (int o = 1; o < 32; o <<= 1) {
            int y = __shfl_up_sync(0xFFFFFFFFu, ws, o);
            if (lane >= o) ws += y;
        }
        warp_sums[lane] = ws;
    }
    __syncthreads();
    int excl = (x - run) + (wid > 0 ? warp_sums[wid - 1] : 0);

    if (t == 0) g_offs[0] = 0;
#pragma unroll
    for (int j = 0; j < SCAN_PER; j++) {
        int idx = i0 + j;
        if (idx < NNODES) g_offs[idx + 1] = excl + deg[j];
    }
}

__global__ void fill_csr_kernel(const int* __restrict__ esrc, const int* __restrict__ edst) {
    int e = blockIdx.x * blockDim.x + threadIdx.x;
    if (e < NEDGE) {
        int s = esrc[e], d = edst[e];
        int pos = g_offs[d] + atomicAdd(&g_cursor[d], 1);
        float w = g_dinv_out[s] * g_dinv_in[d];
        g_edge[pos] = make_int2(s << 11, __float_as_int(w));   // byte offset of row (2048 B/row)
    }
}

// ---------------- aggregation: gather fp16 x (uint4/thread), fp32 acc, fp16 out ----------------
// 128 threads/block, 8 halfs per thread. Layer-1 pass also re-zeroes g_cursor.
template<bool ENT_ONLY>
__global__ void __launch_bounds__(128) aggregate_kernel() {
    int orow = blockIdx.x;
    int node = ENT_ONLY ? ((orow / NE) * NPB + NM + (orow % NE)) : orow;
    int t = threadIdx.x;
    int beg = g_offs[node], end = g_offs[node + 1];

    if (!ENT_ONLY && t == 0) g_cursor[node] = 0;

    __shared__ int2 s_e[128];
    const char* xb = (const char*)g_xh + (uint32_t)(t * 16);   // loop-invariant lane base

    float2 a0 = make_float2(0.f, 0.f), a1 = a0, a2 = a0, a3 = a0;
    for (int base = beg; base < end; base += 128) {
        int n = end - base; if (n > 128) n = 128;
        if (t < n) s_e[t] = g_edge[base + t];
        __syncthreads();
#pragma unroll 4
        for (int i = 0; i < n; i++) {
            int2 e = s_e[i];
            float ww = __int_as_float(e.y);
            uint4 u = *(const uint4*)(xb + (uint32_t)e.x);     // 32-bit add, no IMAD
            float2 f0 = __half22float2(*(__half2*)&u.x);
            float2 f1 = __half22float2(*(__half2*)&u.y);
            float2 f2 = __half22float2(*(__half2*)&u.z);
            float2 f3 = __half22float2(*(__half2*)&u.w);
            a0.x += ww * f0.x; a0.y += ww * f0.y;
            a1.x += ww * f1.x; a1.y += ww * f1.y;
            a2.x += ww * f2.x; a2.y += ww * f2.y;
            a3.x += ww * f3.x; a3.y += ww * f3.y;
        }
        __syncthreads();
    }
    uint4 o;
    *(__half2*)&o.x = __floats2half2_rn(a0.x, a0.y);
    *(__half2*)&o.y = __floats2half2_rn(a1.x, a1.y);
    *(__half2*)&o.z = __floats2half2_rn(a2.x, a2.y);
    *(__half2*)&o.w = __floats2half2_rn(a3.x, a3.y);
    ((uint4*)g_ah)[(size_t)orow * 128 + t] = o;
}

// ---------------- HMMA fp16 GEMM: CTA 128x128, warp tile 64x32, BK=32, 4-stage ----------------
#define BM 128
#define BN 128
#define BK 32
#define SKB 40
#define TILE_E (BM * SKB)                 // 5120 halfs = 10240 B
#define NST 4
#define GEMM_SMEM (NST * 2 * TILE_E * 2)  // 81920 B -> 2 CTAs/SM

template<bool OUT_HALF>
__global__ void __launch_bounds__(256, 2)
mma_gemm_kernel(const __half* __restrict__ A, const __half* __restrict__ B,
                const float* __restrict__ bias, void* __restrict__ CoutV,
                int Nout, int relu) {
    extern __shared__ __half sm[];
    uint32_t sbase = smem_u32(sm);

    const int t = threadIdx.x, lane = t & 31, wid = t >> 5;
    const int wm = wid & 1, wn = wid >> 1;
    const int row0 = blockIdx.y * BM, col0 = blockIdx.x * BN;

    const int r = t >> 1, cpair = (t & 1) * 2;
    const uint4* gA = (const uint4*)A + (size_t)(row0 + r) * 128;  // row pitch: 1024 halfs
    const uint4* gB = (const uint4*)B + (size_t)(col0 + r) * 128;
    const uint32_t so0 = (uint32_t)(r * SKB + cpair * 8) * 2;
    const uint32_t so1 = so0 + 16;

    float acc[4][4][4];
#pragma unroll
    for (int mt = 0; mt < 4; mt++)
#pragma unroll
        for (int nt = 0; nt < 4; nt++)
#pragma unroll
            for (int k = 0; k < 4; k++) acc[mt][nt][k] = 0.f;

    const int nk = 1024 / BK;   // 32

#define ISSUE(k0, st) do { \
        int off = (k0) * 4 + cpair; \
        uint32_t sb_ = sbase + (uint32_t)((st) * 2 * TILE_E * 2); \
        CP16(sb_ + so0, gA + off); CP16(sb_ + so1, gA + off + 1); \
        CP16(sb_ + TILE_E * 2 + so0, gB + off); CP16(sb_ + TILE_E * 2 + so1, gB + off + 1); \
    } while (0)

    ISSUE(0, 0); CP_COMMIT();
    ISSUE(1, 1); CP_COMMIT();
    ISSUE(2, 2); CP_COMMIT();

    const int asel = lane >> 3;
    const int arowoff = (asel & 1) * 8 + (lane & 7);
    const int akadd = (asel >> 1) * 8;
    const int brow2 = ((lane >> 4) & 1) * 8 + (lane & 7);
    const int bk2   = ((lane >> 3) & 1) * 8;

    for (int k0 = 0; k0 < nk; k0++) {
        CP_WAIT2();
        __syncthreads();
        if (k0 + 3 < nk) ISSUE(k0 + 3, (k0 + 3) & 3);
        CP_COMMIT();

        uint32_t base = sbase + (uint32_t)((k0 & 3) * 2 * TILE_E * 2);
        uint32_t bA = base;
        uint32_t bB = base + TILE_E * 2;
#pragma unroll
        for (int ks = 0; ks < 2; ks++) {
            const int kk = ks * 16;
            uint32_t ah[4][4], bb[4][2];
#pragma unroll
            for (int mt = 0; mt < 4; mt++) {
                int rrow = wm * 64 + mt * 16 + arowoff;
                LDSM4(ah[mt], bA + (uint32_t)((rrow * SKB + kk + akadd) * 2));
            }
#pragma unroll
            for (int ntp = 0; ntp < 2; ntp++) {
                int nrow = wn * 32 + ntp * 16 + brow2;
                LDSM4(&bb[2 * ntp][0], bB + (uint32_t)((nrow * SKB + kk + bk2) * 2));
            }
#pragma unroll
            for (int mt = 0; mt < 4; mt++)
#pragma unroll
                for (int nt = 0; nt < 4; nt++) MMA16816(acc[mt][nt], ah[mt], bb[nt]);
        }
    }
#undef ISSUE

    // epilogue
    const int rbase = row0 + wm * 64 + (lane >> 2);
    const int cbase = col0 + wn * 32 + (lane & 3) * 2;
#pragma unroll
    for (int nt = 0; nt < 4; nt++) {
        int col = cbase + nt * 8;
        float b0 = bias[col], b1 = bias[col + 1];
#pragma unroll
        for (int mt = 0; mt < 4; mt++) {
            int rrow = rbase + mt * 16;
            float v0 = acc[mt][nt][0] + b0;
            float v1 = acc[mt][nt][1] + b1;
            float v2 = acc[mt][nt][2] + b0;
            float v3 = acc[mt][nt][3] + b1;
            if (relu) {
                v0 = (v0 > 0.f) ? v0 : LRELU * v0;
                v1 = (v1 > 0.f) ? v1 : LRELU * v1;
                v2 = (v2 > 0.f) ? v2 : LRELU * v2;
                v3 = (v3 > 0.f) ? v3 : LRELU * v3;
            }
            if (OUT_HALF) {
                __half* C = (__half*)CoutV;
                *(__half2*)(C + (size_t)rrow * Nout + col) = __floats2half2_rn(v0, v1);
                *(__half2*)(C + (size_t)(rrow + 8) * Nout + col) = __floats2half2_rn(v2, v3);
            } else {
                float* C = (float*)CoutV;
                *(float2*)(C + (size_t)rrow * Nout + col) = make_float2(v0, v1);
                *(float2*)(C + (size_t)(rrow + 8) * Nout + col) = make_float2(v2, v3);
            }
        }
    }
}

// ---------------- launch ----------------
extern "C" void kernel_launch(void* const* d_in, const int* in_sizes, int n_in,
                              void* d_out, int out_size) {
    const float* mhs  = (const float*)d_in[0];
    const float* ehs  = (const float*)d_in[1];
    const float* shs  = (const float*)d_in[2];
    const int*   esrc = (const int*)d_in[3];
    const int*   edst = (const int*)d_in[4];
    const float* temb = (const float*)d_in[5];
    const float* lns  = (const float*)d_in[6];
    const float* lnb  = (const float*)d_in[7];
    const float* gw   = (const float*)d_in[8];
    const float* gb   = (const float*)d_in[9];
    const float* fcw  = (const float*)d_in[10];
    const float* fcb  = (const float*)d_in[11];
    float* out = (float*)d_out;

    cudaFuncSetAttribute(mma_gemm_kernel<true>,
                         cudaFuncAttributeMaxDynamicSharedMemorySize, GEMM_SMEM);
    cudaFuncSetAttribute(mma_gemm_kernel<false>,
                         cudaFuncAttributeMaxDynamicSharedMemorySize, GEMM_SMEM);

    __half *wt, *fcw_h, *ah, *xh;
    cudaGetSymbolAddress((void**)&wt,    g_wt);
    cudaGetSymbolAddress((void**)&fcw_h, g_fcw);
    cudaGetSymbolAddress((void**)&ah,    g_ah);
    cudaGetSymbolAddress((void**)&xh,    g_xh);

    fused_prep_kernel<<<NNODES + TBLKS + DBLKS, 256>>>(
        mhs, ehs, shs, temb, lns, lnb, gw, fcw, esrc, edst);
    scan_dinv_kernel<<<1, 1024>>>();
    fill_csr_kernel<<<(NEDGE + 255) / 256, 256>>>(esrc, edst);

    // layers 1-2: full node set
    for (int l = 0; l < NLAYER - 1; l++) {
        aggregate_kernel<false><<<NNODES, 128>>>();
        mma_gemm_kernel<true><<<dim3(DDIM / BN, NNODES / BM), 256, GEMM_SMEM>>>(
            ah, wt + (size_t)l * DDIM * DDIM, gb + (size_t)l * DDIM, xh, DDIM, /*relu=*/1);
    }

    // layer 3: entity dst rows only (compact M = 6400)
    aggregate_kernel<true><<<NENT, 128>>>();
    mma_gemm_kernel<true><<<dim3(DDIM / BN, NENT / BM), 256, GEMM_SMEM>>>(
        ah, wt + (size_t)2 * DDIM * DDIM, gb + (size_t)2 * DDIM, xh, DDIM, /*relu=*/1);

    // fc on compact entity rows
    mma_gemm_kernel<false><<<dim3(OUTF / BN, NENT / BM), 256, GEMM_SMEM>>>(
        xh, fcw_h, fcb, out, OUTF, /*relu=*/0);
}